// round 15
// baseline (speedup 1.0000x reference)
#include <cuda_runtime.h>
#include <cuda_fp16.h>
#include <cstdint>
#include <cstddef>

#define BATCH   16384
#define NEMBD   1568
#define KPAD    1600                 // 25 * 64
#define NQKV    384
#define HS      128
#define KTILE   64                   // fp16 per k-tile = 128 B row (SW128 XOR)
#define NKT     (KPAD / KTILE)       // 25 (last tile half-used: k 1536..1568)
#define PIPE    4
#define MTILE   64                   // CTA rows
#define A_BYTES 8192                 // 64x64 fp16
#define B_BYTES 16384                // 128x64 fp16
#define SMEM_STAGE  (A_BYTES + B_BYTES)         // 24KB
#define SMEM_BYTES  (PIPE * SMEM_STAGE + 1024)  // buffers + align-up slack
#define MT      8                    // Taylor terms
#define NTHR    256                  // 8 warps

// ---------------- device-global scratch -------------------------------------
// NOTE: zero-initialized at module load; the pad region k in [1568,1600) of
// g_Bh is never written and must stay zero (read by cpB at kt=24).
__device__ unsigned short g_Bh[(size_t)NQKV * KPAD];   // fp16 W^T
__device__ float          g_qkv[(size_t)BATCH * NQKV];

// ---------------- helpers ----------------------------------------------------
__device__ __forceinline__ uint32_t smem_u32(const void* p) {
    uint32_t a;
    asm("{ .reg .u64 t; cvta.to.shared.u64 t, %1; cvt.u32.u64 %0, t; }"
        : "=r"(a) : "l"(p));
    return a;
}
__device__ __forceinline__ void cp16(uint32_t dst, const void* src) {
    asm volatile("cp.async.cg.shared.global [%0], [%1], 16;" :: "r"(dst), "l"(src));
}
__device__ __forceinline__ void ldsm4(uint32_t* r, uint32_t addr) {
    asm volatile("ldmatrix.sync.aligned.m8n8.x4.shared.b16 {%0,%1,%2,%3}, [%4];"
                 : "=r"(r[0]), "=r"(r[1]), "=r"(r[2]), "=r"(r[3]) : "r"(addr));
}
__device__ __forceinline__ void mma_f32(float* c, const uint32_t* a,
                                        const uint32_t* b) {
    asm volatile(
        "mma.sync.aligned.m16n8k16.row.col.f32.f16.f16.f32 "
        "{%0,%1,%2,%3}, {%4,%5,%6,%7}, {%8,%9}, {%0,%1,%2,%3};"
        : "+f"(c[0]), "+f"(c[1]), "+f"(c[2]), "+f"(c[3])
        : "r"(a[0]), "r"(a[1]), "r"(a[2]), "r"(a[3]), "r"(b[0]), "r"(b[1]));
}
__device__ __forceinline__ uint32_t swz(uint32_t off) {
    return off ^ ((off >> 3) & 0x70);
}

// ---------------- prep W: 588-block coalesced smem transpose --------------------
// grid (196, 3): tile = [8 k x 128 n], 1568 = 196*8 exactly (no guard).
// One coalesced float4 wave -> bar -> 2 packed fp16x2 stores per thread.
__global__ __launch_bounds__(256) void prep_w(const float* __restrict__ wq,
                                              const float* __restrict__ wk,
                                              const float* __restrict__ wv) {
    __shared__ float s[8][132];
    const float* w = (blockIdx.y == 0) ? wq : ((blockIdx.y == 1) ? wk : wv);
    int k0  = blockIdx.x * 8;
    int tid = threadIdx.x;
    {                                             // 256 float4 loads, coalesced
        int r = tid >> 5, c4 = tid & 31;
        *reinterpret_cast<float4*>(&s[r][c4 * 4]) =
            *reinterpret_cast<const float4*>(w + (size_t)(k0 + r) * HS + c4 * 4);
    }
    __syncthreads();
#pragma unroll
    for (int i = 0; i < 2; i++) {                 // 512 uint32 writes
        int idx = tid + i * 256;
        int n = idx >> 2, p = idx & 3;
        unsigned short h0 = __half_as_ushort(__float2half_rn(s[2 * p][n]));
        unsigned short h1 = __half_as_ushort(__float2half_rn(s[2 * p + 1][n]));
        *reinterpret_cast<uint32_t*>(
            g_Bh + (size_t)(blockIdx.y * HS + n) * KPAD + k0 + 2 * p) =
            (uint32_t)h0 | ((uint32_t)h1 << 16);
    }
}

// ---------------- GEMM (R14 structure, unchanged) --------------------------------
// CTA 64x128 (8 warps, warp tile 32x32), grid (3, 256) n-fastest, 768 CTAs,
// 2 CTAs/SM, single __syncthreads per k-iter, PIPE=4 cp.async.
// kt 0..23 full; kt 24 computes only ks 0..1 (k 1536..1568) — rest is zero pad.

__device__ __forceinline__ void ldgA(const float* __restrict__ x, int kt, int m0,
                                     float4 va[2][2]) {
    int k0 = kt * KTILE;
    int tid = threadIdx.x;
#pragma unroll
    for (int i = 0; i < 2; i++) {
        int idx = tid + i * NTHR;
        int r = idx >> 3, c = idx & 7;
        int k = k0 + c * 8;
        if (k < NEMBD) {
            const float4* s =
                reinterpret_cast<const float4*>(x + (size_t)(m0 + r) * NEMBD + k);
            va[i][0] = s[0];
            va[i][1] = s[1];
        } else {
            va[i][0] = make_float4(0.f, 0.f, 0.f, 0.f);
            va[i][1] = make_float4(0.f, 0.f, 0.f, 0.f);
        }
    }
}

__device__ __forceinline__ void stsA(uint32_t st, const float4 va[2][2]) {
    int tid = threadIdx.x;
#pragma unroll
    for (int i = 0; i < 2; i++) {
        int idx = tid + i * NTHR;
        int r = idx >> 3, c = idx & 7;
        float f[8] = {va[i][0].x, va[i][0].y, va[i][0].z, va[i][0].w,
                      va[i][1].x, va[i][1].y, va[i][1].z, va[i][1].w};
        uint32_t hp[4];
#pragma unroll
        for (int q = 0; q < 4; q++) {
            __half h0 = __float2half_rn(f[2 * q]);
            __half h1 = __float2half_rn(f[2 * q + 1]);
            hp[q] = (uint32_t)__half_as_ushort(h0) |
                    ((uint32_t)__half_as_ushort(h1) << 16);
        }
        uint32_t so = swz((uint32_t)(r * 128 + c * 16));
        asm volatile("st.shared.v4.b32 [%0], {%1,%2,%3,%4};"
                     :: "r"(st + so), "r"(hp[0]), "r"(hp[1]), "r"(hp[2]), "r"(hp[3]));
    }
}

__device__ __forceinline__ void cpB(int kt, uint32_t st) {
    int k0 = kt * KTILE;
    int n0 = blockIdx.x * 128;
    int tid = threadIdx.x;
#pragma unroll
    for (int i = 0; i < 4; i++) {
        int idx = tid + i * NTHR;
        int r = idx >> 3, c = idx & 7;
        uint32_t so = swz((uint32_t)(r * 128 + c * 16));
        cp16(st + A_BYTES + so,
             g_Bh + (size_t)(n0 + r) * KPAD + k0 + c * 8);
    }
    asm volatile("cp.async.commit_group;" ::: "memory");
}

__global__ __launch_bounds__(NTHR, 2) void gemm_qkv(const float* __restrict__ x) {
    extern __shared__ char smem[];
    uint32_t s0 = (smem_u32(smem) + 1023) & ~1023u;
    int tid = threadIdx.x;
    int wid = tid >> 5;
    int lid = tid & 31;
    int m0  = blockIdx.y * MTILE;

    int wm = (wid & 1) * 32;
    int wn = (wid >> 1) * 32;

    float acc[2][4][4];
#pragma unroll
    for (int mi = 0; mi < 2; mi++)
#pragma unroll
        for (int nt = 0; nt < 4; nt++)
#pragma unroll
            for (int q = 0; q < 4; q++) acc[mi][nt][q] = 0.f;

    uint32_t aRow = (uint32_t)(wm + (lid & 15));
    uint32_t aByt = (uint32_t)((lid >> 4) << 4);
    uint32_t bRow = (uint32_t)(wn + ((lid >> 4) << 3) + (lid & 7));
    uint32_t bByt = (uint32_t)(((lid >> 3) & 1) << 4);

    float4 vcur[2][2];
    {
        float4 vt[2][2];
#pragma unroll
        for (int s = 0; s < PIPE - 1; s++) {
            uint32_t st = s0 + s * SMEM_STAGE;
            ldgA(x, s, m0, vt);
            stsA(st, vt);
            cpB(s, st);
        }
    }
    ldgA(x, PIPE - 1, m0, vcur);

    for (int kt = 0; kt < NKT - 1; kt++) {        // kt 0..23 full tiles
        if (kt < NKT - 2) asm volatile("cp.async.wait_group 2;" ::: "memory");
        else              asm volatile("cp.async.wait_group 1;" ::: "memory");
        __syncthreads();

        if (kt <= NKT - PIPE) {                   // produce stage kt+3 (<=24)
            uint32_t stp = s0 + ((kt + PIPE - 1) % PIPE) * SMEM_STAGE;
            stsA(stp, vcur);
            cpB(kt + PIPE - 1, stp);
        }
        if (kt <= NKT - PIPE - 1)                 // prefetch A of stage kt+4
            ldgA(x, kt + PIPE, m0, vcur);

        uint32_t st = s0 + (kt % PIPE) * SMEM_STAGE;
#pragma unroll
        for (int ks = 0; ks < 4; ks++) {
            uint32_t kb = (uint32_t)(ks * 32);
            uint32_t ah[2][4], bh[2][4];
#pragma unroll
            for (int mi = 0; mi < 2; mi++) {
                uint32_t row = aRow + mi * 16;
                uint32_t byt = kb + aByt;
                ldsm4(ah[mi], st + row * 128 + (byt ^ ((row & 7) << 4)));
            }
#pragma unroll
            for (int g = 0; g < 2; g++) {
                uint32_t row = bRow + g * 16;
                uint32_t byt = kb + bByt;
                ldsm4(bh[g], st + A_BYTES + row * 128 +
                             (byt ^ ((row & 7) << 4)));
            }
#pragma unroll
            for (int mi = 0; mi < 2; mi++)
#pragma unroll
                for (int nt = 0; nt < 4; nt++)
                    mma_f32(acc[mi][nt], ah[mi], &bh[nt >> 1][(nt & 1) * 2]);
        }
    }

    // kt = 24: half tile, only ks 0..1 carry data (k 1536..1568)
    asm volatile("cp.async.wait_group 0;" ::: "memory");
    __syncthreads();
    {
        uint32_t st = s0 + ((NKT - 1) % PIPE) * SMEM_STAGE;
#pragma unroll
        for (int ks = 0; ks < 2; ks++) {
            uint32_t kb = (uint32_t)(ks * 32);
            uint32_t ah[2][4], bh[2][4];
#pragma unroll
            for (int mi = 0; mi < 2; mi++) {
                uint32_t row = aRow + mi * 16;
                uint32_t byt = kb + aByt;
                ldsm4(ah[mi], st + row * 128 + (byt ^ ((row & 7) << 4)));
            }
#pragma unroll
            for (int g = 0; g < 2; g++) {
                uint32_t row = bRow + g * 16;
                uint32_t byt = kb + bByt;
                ldsm4(bh[g], st + A_BYTES + row * 128 +
                             (byt ^ ((row & 7) << 4)));
            }
#pragma unroll
            for (int mi = 0; mi < 2; mi++)
#pragma unroll
                for (int nt = 0; nt < 4; nt++)
                    mma_f32(acc[mi][nt], ah[mi], &bh[nt >> 1][(nt & 1) * 2]);
        }
    }

    int n0 = blockIdx.x * 128;
    int rbase = m0 + wm + (lid >> 2);
    int cbase = n0 + wn + (lid & 3) * 2;
#pragma unroll
    for (int mi = 0; mi < 2; mi++)
#pragma unroll
        for (int nt = 0; nt < 4; nt++) {
            float* d0 = g_qkv + (size_t)(rbase + mi * 16) * NQKV + cbase + nt * 8;
            float* d1 = d0 + 8 * NQKV;
            *reinterpret_cast<float2*>(d0) =
                make_float2(acc[mi][nt][0], acc[mi][nt][1]);
            *reinterpret_cast<float2*>(d1) =
                make_float2(acc[mi][nt][2], acc[mi][nt][3]);
        }
}

// ---------------- attention: Taylor-moment softmax (float4 I/O) ------------------
__global__ __launch_bounds__(256) void attn_kernel(float* __restrict__ out) {
    int b    = blockIdx.x * 8 + (threadIdx.x >> 5);
    int lane = threadIdx.x & 31;
    const float* base = g_qkv + (size_t)b * NQKV;

    float4 k4 = *reinterpret_cast<const float4*>(base + HS + lane * 4);
    float4 v4 = *reinterpret_cast<const float4*>(base + 2 * HS + lane * 4);
    float kj[4] = {k4.x, k4.y, k4.z, k4.w};
    float vj[4] = {v4.x, v4.y, v4.z, v4.w};

    float C[MT + 1], D[MT + 1];
#pragma unroll
    for (int m = 0; m <= MT; m++) { C[m] = 0.f; D[m] = 0.f; }
#pragma unroll
    for (int e = 0; e < 4; e++) {
        float p = 1.f;
        C[0] += vj[e];
        D[0] += 1.f;
#pragma unroll
        for (int m = 1; m <= MT; m++) {
            p *= kj[e];
            D[m] += p;
            C[m] = fmaf(p, vj[e], C[m]);
        }
    }
#pragma unroll
    for (int off = 16; off > 0; off >>= 1) {
#pragma unroll
        for (int m = 0; m <= MT; m++) {
            C[m] += __shfl_xor_sync(0xFFFFFFFFu, C[m], off);
            D[m] += __shfl_xor_sync(0xFFFFFFFFu, D[m], off);
        }
    }
    const float invf[MT + 1] = {1.f, 1.f, 0.5f, 1.f / 6.f, 1.f / 24.f, 1.f / 120.f,
                                1.f / 720.f, 1.f / 5040.f, 1.f / 40320.f};
#pragma unroll
    for (int m = 2; m <= MT; m++) { C[m] *= invf[m]; D[m] *= invf[m]; }

    float4 q4 = *reinterpret_cast<const float4*>(base + lane * 4);
    float tq[4] = {q4.x, q4.y, q4.z, q4.w};
    float4 o;
    float* op = &o.x;
#pragma unroll
    for (int e = 0; e < 4; e++) {
        float t = tq[e] * 0.02525381361380527f;        // 1/sqrt(1568)
        float num = C[MT], den = D[MT];
#pragma unroll
        for (int m = MT - 1; m >= 0; m--) {
            num = fmaf(num, t, C[m]);
            den = fmaf(den, t, D[m]);
        }
        op[e] = num / den;
    }
    *reinterpret_cast<float4*>(out + (size_t)b * HS + lane * 4) = o;
}

// ---------------- launch ----------------------------------------------------------
extern "C" void kernel_launch(void* const* d_in, const int* in_sizes, int n_in,
                              void* d_out, int out_size) {
    const float* x  = (const float*)d_in[0];
    const float* wq = (const float*)d_in[1];
    const float* wk = (const float*)d_in[2];
    const float* wv = (const float*)d_in[3];
    float* out = (float*)d_out;

    static bool attr_set = false;
    if (!attr_set) {
        cudaFuncSetAttribute(gemm_qkv, cudaFuncAttributeMaxDynamicSharedMemorySize,
                             SMEM_BYTES);
        attr_set = true;
    }

    dim3 wgrid(196, 3);
    prep_w<<<wgrid, 256>>>(wq, wk, wv);
    dim3 grid(NQKV / 128, BATCH / MTILE);
    gemm_qkv<<<grid, NTHR, SMEM_BYTES>>>(x);
    attn_kernel<<<BATCH / 8, 256>>>(out);
}

// round 16
// speedup vs baseline: 1.0091x; 1.0091x over previous
#include <cuda_runtime.h>
#include <cuda_fp16.h>
#include <cstdint>
#include <cstddef>

#define BATCH   16384
#define NEMBD   1568
#define KPAD    1600                 // 25 * 64
#define NQKV    384
#define HS      128
#define KTILE   64                   // fp16 per k-tile = 128 B row (SW128 XOR)
#define NKT     (KPAD / KTILE)       // 25 (last tile half-used: k 1536..1568)
#define PIPE    4
#define MTILE   64                   // CTA rows
#define A_BYTES 8192                 // 64x64 fp16
#define B_BYTES 16384                // 128x64 fp16
#define SMEM_STAGE  (A_BYTES + B_BYTES)         // 24KB
#define SMEM_BYTES  (PIPE * SMEM_STAGE + 1024)  // buffers + align-up slack
#define MT      8                    // Taylor terms
#define NTHR    256                  // 8 warps

// ---------------- device-global scratch -------------------------------------
// NOTE: zero-initialized at module load; the pad region k in [1568,1600) of
// g_Bh is never written and must stay zero (read by cpB at kt=24).
__device__ unsigned short g_Bh[(size_t)NQKV * KPAD];   // fp16 W^T
__device__ __half         g_qkv[(size_t)BATCH * NQKV]; // fp16 q|k|v scratch

// ---------------- helpers ----------------------------------------------------
__device__ __forceinline__ uint32_t smem_u32(const void* p) {
    uint32_t a;
    asm("{ .reg .u64 t; cvta.to.shared.u64 t, %1; cvt.u32.u64 %0, t; }"
        : "=r"(a) : "l"(p));
    return a;
}
__device__ __forceinline__ void cp16(uint32_t dst, const void* src) {
    asm volatile("cp.async.cg.shared.global [%0], [%1], 16;" :: "r"(dst), "l"(src));
}
__device__ __forceinline__ void ldsm4(uint32_t* r, uint32_t addr) {
    asm volatile("ldmatrix.sync.aligned.m8n8.x4.shared.b16 {%0,%1,%2,%3}, [%4];"
                 : "=r"(r[0]), "=r"(r[1]), "=r"(r[2]), "=r"(r[3]) : "r"(addr));
}
__device__ __forceinline__ void mma_f32(float* c, const uint32_t* a,
                                        const uint32_t* b) {
    asm volatile(
        "mma.sync.aligned.m16n8k16.row.col.f32.f16.f16.f32 "
        "{%0,%1,%2,%3}, {%4,%5,%6,%7}, {%8,%9}, {%0,%1,%2,%3};"
        : "+f"(c[0]), "+f"(c[1]), "+f"(c[2]), "+f"(c[3])
        : "r"(a[0]), "r"(a[1]), "r"(a[2]), "r"(a[3]), "r"(b[0]), "r"(b[1]));
}
__device__ __forceinline__ uint32_t swz(uint32_t off) {
    return off ^ ((off >> 3) & 0x70);
}

// ---------------- prep W: 588-block coalesced smem transpose --------------------
// grid (196, 3): tile = [8 k x 128 n], 1568 = 196*8 exactly (no guard).
__global__ __launch_bounds__(256) void prep_w(const float* __restrict__ wq,
                                              const float* __restrict__ wk,
                                              const float* __restrict__ wv) {
    __shared__ float s[8][132];
    const float* w = (blockIdx.y == 0) ? wq : ((blockIdx.y == 1) ? wk : wv);
    int k0  = blockIdx.x * 8;
    int tid = threadIdx.x;
    {                                             // 256 float4 loads, coalesced
        int r = tid >> 5, c4 = tid & 31;
        *reinterpret_cast<float4*>(&s[r][c4 * 4]) =
            *reinterpret_cast<const float4*>(w + (size_t)(k0 + r) * HS + c4 * 4);
    }
    __syncthreads();
#pragma unroll
    for (int i = 0; i < 2; i++) {                 // 512 uint32 writes
        int idx = tid + i * 256;
        int n = idx >> 2, p = idx & 3;
        unsigned short h0 = __half_as_ushort(__float2half_rn(s[2 * p][n]));
        unsigned short h1 = __half_as_ushort(__float2half_rn(s[2 * p + 1][n]));
        *reinterpret_cast<uint32_t*>(
            g_Bh + (size_t)(blockIdx.y * HS + n) * KPAD + k0 + 2 * p) =
            (uint32_t)h0 | ((uint32_t)h1 << 16);
    }
}

// ---------------- GEMM (R14 structure; fp16 epilogue) ----------------------------
// CTA 64x128 (8 warps, warp tile 32x32), grid (3, 256) n-fastest, 768 CTAs,
// 2 CTAs/SM, single __syncthreads per k-iter, PIPE=4 cp.async.
// kt 0..23 full; kt 24 computes only ks 0..1 (k 1536..1568) — rest is zero pad.

__device__ __forceinline__ void ldgA(const float* __restrict__ x, int kt, int m0,
                                     float4 va[2][2]) {
    int k0 = kt * KTILE;
    int tid = threadIdx.x;
#pragma unroll
    for (int i = 0; i < 2; i++) {
        int idx = tid + i * NTHR;
        int r = idx >> 3, c = idx & 7;
        int k = k0 + c * 8;
        if (k < NEMBD) {
            const float4* s =
                reinterpret_cast<const float4*>(x + (size_t)(m0 + r) * NEMBD + k);
            va[i][0] = s[0];
            va[i][1] = s[1];
        } else {
            va[i][0] = make_float4(0.f, 0.f, 0.f, 0.f);
            va[i][1] = make_float4(0.f, 0.f, 0.f, 0.f);
        }
    }
}

__device__ __forceinline__ void stsA(uint32_t st, const float4 va[2][2]) {
    int tid = threadIdx.x;
#pragma unroll
    for (int i = 0; i < 2; i++) {
        int idx = tid + i * NTHR;
        int r = idx >> 3, c = idx & 7;
        float f[8] = {va[i][0].x, va[i][0].y, va[i][0].z, va[i][0].w,
                      va[i][1].x, va[i][1].y, va[i][1].z, va[i][1].w};
        uint32_t hp[4];
#pragma unroll
        for (int q = 0; q < 4; q++) {
            __half h0 = __float2half_rn(f[2 * q]);
            __half h1 = __float2half_rn(f[2 * q + 1]);
            hp[q] = (uint32_t)__half_as_ushort(h0) |
                    ((uint32_t)__half_as_ushort(h1) << 16);
        }
        uint32_t so = swz((uint32_t)(r * 128 + c * 16));
        asm volatile("st.shared.v4.b32 [%0], {%1,%2,%3,%4};"
                     :: "r"(st + so), "r"(hp[0]), "r"(hp[1]), "r"(hp[2]), "r"(hp[3]));
    }
}

__device__ __forceinline__ void cpB(int kt, uint32_t st) {
    int k0 = kt * KTILE;
    int n0 = blockIdx.x * 128;
    int tid = threadIdx.x;
#pragma unroll
    for (int i = 0; i < 4; i++) {
        int idx = tid + i * NTHR;
        int r = idx >> 3, c = idx & 7;
        uint32_t so = swz((uint32_t)(r * 128 + c * 16));
        cp16(st + A_BYTES + so,
             g_Bh + (size_t)(n0 + r) * KPAD + k0 + c * 8);
    }
    asm volatile("cp.async.commit_group;" ::: "memory");
}

__global__ __launch_bounds__(NTHR, 2) void gemm_qkv(const float* __restrict__ x) {
    extern __shared__ char smem[];
    uint32_t s0 = (smem_u32(smem) + 1023) & ~1023u;
    int tid = threadIdx.x;
    int wid = tid >> 5;
    int lid = tid & 31;
    int m0  = blockIdx.y * MTILE;

    int wm = (wid & 1) * 32;
    int wn = (wid >> 1) * 32;

    float acc[2][4][4];
#pragma unroll
    for (int mi = 0; mi < 2; mi++)
#pragma unroll
        for (int nt = 0; nt < 4; nt++)
#pragma unroll
            for (int q = 0; q < 4; q++) acc[mi][nt][q] = 0.f;

    uint32_t aRow = (uint32_t)(wm + (lid & 15));
    uint32_t aByt = (uint32_t)((lid >> 4) << 4);
    uint32_t bRow = (uint32_t)(wn + ((lid >> 4) << 3) + (lid & 7));
    uint32_t bByt = (uint32_t)(((lid >> 3) & 1) << 4);

    float4 vcur[2][2];
    {
        float4 vt[2][2];
#pragma unroll
        for (int s = 0; s < PIPE - 1; s++) {
            uint32_t st = s0 + s * SMEM_STAGE;
            ldgA(x, s, m0, vt);
            stsA(st, vt);
            cpB(s, st);
        }
    }
    ldgA(x, PIPE - 1, m0, vcur);

    for (int kt = 0; kt < NKT - 1; kt++) {        // kt 0..23 full tiles
        if (kt < NKT - 2) asm volatile("cp.async.wait_group 2;" ::: "memory");
        else              asm volatile("cp.async.wait_group 1;" ::: "memory");
        __syncthreads();

        if (kt <= NKT - PIPE) {                   // produce stage kt+3 (<=24)
            uint32_t stp = s0 + ((kt + PIPE - 1) % PIPE) * SMEM_STAGE;
            stsA(stp, vcur);
            cpB(kt + PIPE - 1, stp);
        }
        if (kt <= NKT - PIPE - 1)                 // prefetch A of stage kt+4
            ldgA(x, kt + PIPE, m0, vcur);

        uint32_t st = s0 + (kt % PIPE) * SMEM_STAGE;
#pragma unroll
        for (int ks = 0; ks < 4; ks++) {
            uint32_t kb = (uint32_t)(ks * 32);
            uint32_t ah[2][4], bh[2][4];
#pragma unroll
            for (int mi = 0; mi < 2; mi++) {
                uint32_t row = aRow + mi * 16;
                uint32_t byt = kb + aByt;
                ldsm4(ah[mi], st + row * 128 + (byt ^ ((row & 7) << 4)));
            }
#pragma unroll
            for (int g = 0; g < 2; g++) {
                uint32_t row = bRow + g * 16;
                uint32_t byt = kb + bByt;
                ldsm4(bh[g], st + A_BYTES + row * 128 +
                             (byt ^ ((row & 7) << 4)));
            }
#pragma unroll
            for (int mi = 0; mi < 2; mi++)
#pragma unroll
                for (int nt = 0; nt < 4; nt++)
                    mma_f32(acc[mi][nt], ah[mi], &bh[nt >> 1][(nt & 1) * 2]);
        }
    }

    // kt = 24: half tile, only ks 0..1 carry data (k 1536..1568)
    asm volatile("cp.async.wait_group 0;" ::: "memory");
    __syncthreads();
    {
        uint32_t st = s0 + ((NKT - 1) % PIPE) * SMEM_STAGE;
#pragma unroll
        for (int ks = 0; ks < 2; ks++) {
            uint32_t kb = (uint32_t)(ks * 32);
            uint32_t ah[2][4], bh[2][4];
#pragma unroll
            for (int mi = 0; mi < 2; mi++) {
                uint32_t row = aRow + mi * 16;
                uint32_t byt = kb + aByt;
                ldsm4(ah[mi], st + row * 128 + (byt ^ ((row & 7) << 4)));
            }
#pragma unroll
            for (int g = 0; g < 2; g++) {
                uint32_t row = bRow + g * 16;
                uint32_t byt = kb + bByt;
                ldsm4(bh[g], st + A_BYTES + row * 128 +
                             (byt ^ ((row & 7) << 4)));
            }
#pragma unroll
            for (int mi = 0; mi < 2; mi++)
#pragma unroll
                for (int nt = 0; nt < 4; nt++)
                    mma_f32(acc[mi][nt], ah[mi], &bh[nt >> 1][(nt & 1) * 2]);
        }
    }

    // fp16 epilogue: one half2 store per fragment row-pair
    int n0 = blockIdx.x * 128;
    int rbase = m0 + wm + (lid >> 2);
    int cbase = n0 + wn + (lid & 3) * 2;
#pragma unroll
    for (int mi = 0; mi < 2; mi++)
#pragma unroll
        for (int nt = 0; nt < 4; nt++) {
            __half2 h01 = __floats2half2_rn(acc[mi][nt][0], acc[mi][nt][1]);
            __half2 h23 = __floats2half2_rn(acc[mi][nt][2], acc[mi][nt][3]);
            __half* d0 = g_qkv + (size_t)(rbase + mi * 16) * NQKV + cbase + nt * 8;
            *reinterpret_cast<__half2*>(d0) = h01;
            *reinterpret_cast<__half2*>(d0 + 8 * NQKV) = h23;
        }
}

// ---------------- attention: Taylor-moment softmax (fp16 in, fp32 out) -----------
__global__ __launch_bounds__(256) void attn_kernel(float* __restrict__ out) {
    int b    = blockIdx.x * 8 + (threadIdx.x >> 5);
    int lane = threadIdx.x & 31;
    const __half* base = g_qkv + (size_t)b * NQKV;

    __half2 k2[2], v2[2];
    *reinterpret_cast<uint2*>(k2) =
        *reinterpret_cast<const uint2*>(base + HS + lane * 4);
    *reinterpret_cast<uint2*>(v2) =
        *reinterpret_cast<const uint2*>(base + 2 * HS + lane * 4);
    float2 ka = __half22float2(k2[0]), kb2 = __half22float2(k2[1]);
    float2 va = __half22float2(v2[0]), vb2 = __half22float2(v2[1]);
    float kj[4] = {ka.x, ka.y, kb2.x, kb2.y};
    float vj[4] = {va.x, va.y, vb2.x, vb2.y};

    float C[MT + 1], D[MT + 1];
#pragma unroll
    for (int m = 0; m <= MT; m++) { C[m] = 0.f; D[m] = 0.f; }
#pragma unroll
    for (int e = 0; e < 4; e++) {
        float p = 1.f;
        C[0] += vj[e];
        D[0] += 1.f;
#pragma unroll
        for (int m = 1; m <= MT; m++) {
            p *= kj[e];
            D[m] += p;
            C[m] = fmaf(p, vj[e], C[m]);
        }
    }
#pragma unroll
    for (int off = 16; off > 0; off >>= 1) {
#pragma unroll
        for (int m = 0; m <= MT; m++) {
            C[m] += __shfl_xor_sync(0xFFFFFFFFu, C[m], off);
            D[m] += __shfl_xor_sync(0xFFFFFFFFu, D[m], off);
        }
    }
    const float invf[MT + 1] = {1.f, 1.f, 0.5f, 1.f / 6.f, 1.f / 24.f, 1.f / 120.f,
                                1.f / 720.f, 1.f / 5040.f, 1.f / 40320.f};
#pragma unroll
    for (int m = 2; m <= MT; m++) { C[m] *= invf[m]; D[m] *= invf[m]; }

    __half2 q2[2];
    *reinterpret_cast<uint2*>(q2) =
        *reinterpret_cast<const uint2*>(base + lane * 4);
    float2 qa = __half22float2(q2[0]), qb = __half22float2(q2[1]);
    float tq[4] = {qa.x, qa.y, qb.x, qb.y};
    float4 o;
    float* op = &o.x;
#pragma unroll
    for (int e = 0; e < 4; e++) {
        float t = tq[e] * 0.02525381361380527f;        // 1/sqrt(1568)
        float num = C[MT], den = D[MT];
#pragma unroll
        for (int m = MT - 1; m >= 0; m--) {
            num = fmaf(num, t, C[m]);
            den = fmaf(den, t, D[m]);
        }
        op[e] = num / den;
    }
    *reinterpret_cast<float4*>(out + (size_t)b * HS + lane * 4) = o;
}

// ---------------- launch ----------------------------------------------------------
extern "C" void kernel_launch(void* const* d_in, const int* in_sizes, int n_in,
                              void* d_out, int out_size) {
    const float* x  = (const float*)d_in[0];
    const float* wq = (const float*)d_in[1];
    const float* wk = (const float*)d_in[2];
    const float* wv = (const float*)d_in[3];
    float* out = (float*)d_out;

    static bool attr_set = false;
    if (!attr_set) {
        cudaFuncSetAttribute(gemm_qkv, cudaFuncAttributeMaxDynamicSharedMemorySize,
                             SMEM_BYTES);
        attr_set = true;
    }

    dim3 wgrid(196, 3);
    prep_w<<<wgrid, 256>>>(wq, wk, wv);
    dim3 grid(NQKV / 128, BATCH / MTILE);
    gemm_qkv<<<grid, NTHR, SMEM_BYTES>>>(x);
    attn_kernel<<<BATCH / 8, 256>>>(out);
}